// round 5
// baseline (speedup 1.0000x reference)
#include <cuda_runtime.h>

#define N_NODES 50000
#define N_EDGES 800000
#define F_IN    500
#define H       96
#define NCHUNK  ((N_NODES + 1023) / 1024)   // 49

// ---------------- device scratch (no allocations allowed) ----------------
__device__ float d_norm_out[N_NODES];
__device__ float d_norm_in[N_NODES];
__device__ int   d_deg_out[N_NODES];
__device__ int   d_deg_in[N_NODES];
__device__ int   d_row_ptr[N_NODES + 1];
__device__ int   d_cursor[N_NODES];
__device__ int   d_chunksum[NCHUNK];
__device__ int   d_chunkoff[NCHUNK];
__device__ int   d_col[N_EDGES];            // src ids grouped by dst
__device__ int   d_col2[N_EDGES];           // perm[src] grouped by dst (view 2)
__device__ float d_colw[N_EDGES];           // norm_out[src] per edge
__device__ float d_Y[N_NODES * H];          // x @ W1 (shared by both views)
__device__ float d_h[N_NODES * H];
__device__ float d_t[N_NODES * H];
__device__ float d_wvec[H];                 // Wm @ ones
__device__ float d_bsum;                    // sum(bm)

// ---------------- degree / norm ----------------
__global__ void k_zero_deg() {
    int i = blockIdx.x * blockDim.x + threadIdx.x;
    if (i < N_NODES) { d_deg_out[i] = 0; d_deg_in[i] = 0; }
}

__global__ void k_count(const int* __restrict__ src, const int* __restrict__ dst) {
    int e = blockIdx.x * blockDim.x + threadIdx.x;
    if (e < N_EDGES) {
        atomicAdd(&d_deg_out[src[e]], 1);
        atomicAdd(&d_deg_in[dst[e]], 1);
    }
}

__global__ void k_norm() {
    int i = blockIdx.x * blockDim.x + threadIdx.x;
    if (i < N_NODES) {
        int dor = d_deg_out[i]; if (dor < 1) dor = 1;
        int din = d_deg_in[i];  if (din < 1) din = 1;
        d_norm_out[i] = rsqrtf((float)dor);
        d_norm_in[i]  = rsqrtf((float)din);
    }
}

// ---------------- parallel exclusive scan (3 phases) ----------------
// phase 1: per-1024-chunk exclusive scan via warp shuffles; chunk totals out
__global__ void k_scan1() {
    int tid = threadIdx.x;
    int i = blockIdx.x * 1024 + tid;
    int v = (i < N_NODES) ? d_deg_in[i] : 0;
    int lane = tid & 31, wid = tid >> 5;

    int inc = v;
    #pragma unroll
    for (int off = 1; off < 32; off <<= 1) {
        int t = __shfl_up_sync(0xffffffffu, inc, off);
        if (lane >= off) inc += t;
    }
    __shared__ int wsum[32];
    if (lane == 31) wsum[wid] = inc;
    __syncthreads();
    if (wid == 0) {
        int w = wsum[lane];
        #pragma unroll
        for (int off = 1; off < 32; off <<= 1) {
            int t = __shfl_up_sync(0xffffffffu, w, off);
            if (lane >= off) w += t;
        }
        wsum[lane] = w;
    }
    __syncthreads();
    int base = wid ? wsum[wid - 1] : 0;
    if (i < N_NODES) d_row_ptr[i] = base + inc - v;   // chunk-local exclusive
    if (tid == 1023) d_chunksum[blockIdx.x] = base + inc;
}

// phase 2: scan the 49 chunk sums (single tiny block)
__global__ void k_scan2() {
    __shared__ int s[64];
    int tid = threadIdx.x;                  // 64 threads
    int v = (tid < NCHUNK) ? d_chunksum[tid] : 0;
    s[tid] = v;
    __syncthreads();
    #pragma unroll
    for (int off = 1; off < 64; off <<= 1) {
        int t = (tid >= off) ? s[tid - off] : 0;
        __syncthreads();
        s[tid] += t;
        __syncthreads();
    }
    if (tid < NCHUNK) d_chunkoff[tid] = s[tid] - v;   // exclusive
}

// phase 3: add chunk offsets, init cursors, cap row_ptr
__global__ void k_scan3() {
    int i = blockIdx.x * blockDim.x + threadIdx.x;
    if (i < N_NODES) {
        int r = d_row_ptr[i] + d_chunkoff[i >> 10];
        d_row_ptr[i] = r;
        d_cursor[i] = r;
    }
    if (i == 0) d_row_ptr[N_NODES] = N_EDGES;
}

// ---------------- CSR build with folded edge data ----------------
__global__ void k_build_csr(const int* __restrict__ src, const int* __restrict__ dst,
                            const int* __restrict__ perm) {
    int e = blockIdx.x * blockDim.x + threadIdx.x;
    if (e < N_EDGES) {
        int d = dst[e];
        int s = src[e];
        int pos = atomicAdd(&d_cursor[d], 1);
        d_col[pos]  = s;
        d_col2[pos] = perm[s];
        d_colw[pos] = d_norm_out[s];
    }
}

// ---------------- fold Wm into a vector ----------------
__global__ void k_fold(const float* __restrict__ Wm, const float* __restrict__ bm) {
    int j = threadIdx.x;
    if (j < H) {
        float s = 0.f;
        #pragma unroll 4
        for (int k = 0; k < H; k++) s += Wm[j * H + k];
        d_wvec[j] = s;
    }
    if (j == H) {
        float s = 0.f;
        for (int k = 0; k < H; k++) s += bm[k];
        d_bsum = s;
    }
}

// ---------------- SGEMM: C[M,96] = (rowscale .* A[M,K]) @ B[K,96] ----------------
// BM=128, BN=96, BK=16, 256 threads, 8x6 micro-tile, float4 A loads.
__global__ void __launch_bounds__(256) sgemm_n96(
        const float* __restrict__ A, int K,
        const float* __restrict__ B,
        const float* __restrict__ rowscale,
        float* __restrict__ C, int M) {
    const int BM = 128, BK = 16;
    __shared__ float sA[BK][BM + 2];        // pad=2: conflict-free transposed STS
    __shared__ float sB[BK][96];

    int tid = threadIdx.x;
    int tx = tid & 15;                      // 16 col groups (6 cols each)
    int ty = tid >> 4;                      // 16 row groups (8 rows each)
    int bm0 = blockIdx.x * BM;

    int lr = tid >> 2;                      // 0..63 loader row
    int lc4 = tid & 3;                      // 0..3 loader float4-col within BK

    float acc[8][6];
    #pragma unroll
    for (int i = 0; i < 8; i++)
        #pragma unroll
        for (int j = 0; j < 6; j++) acc[i][j] = 0.f;

    // loop-invariant row scales for the two loader rows
    float rsc[2];
    #pragma unroll
    for (int hh = 0; hh < 2; hh++) {
        int gr = bm0 + lr + hh * 64;
        rsc[hh] = 1.f;
        if (rowscale) rsc[hh] = (gr < M) ? rowscale[gr] : 0.f;
    }

    int KF = K & ~(BK - 1);                 // full-tile part of K

    for (int k0 = 0; k0 < KF; k0 += BK) {
        #pragma unroll
        for (int hh = 0; hh < 2; hh++) {
            int r = lr + hh * 64;
            int gr = bm0 + r;
            float4 v = make_float4(0.f, 0.f, 0.f, 0.f);
            if (gr < M)
                v = *(const float4*)&A[gr * K + k0 + lc4 * 4];
            float s = rsc[hh];
            sA[lc4 * 4 + 0][r] = v.x * s;
            sA[lc4 * 4 + 1][r] = v.y * s;
            sA[lc4 * 4 + 2][r] = v.z * s;
            sA[lc4 * 4 + 3][r] = v.w * s;
        }
        #pragma unroll
        for (int hh = 0; hh < 6; hh++) {
            int idx = tid + hh * 256;
            int r = idx / 96, c = idx % 96;
            sB[r][c] = B[(k0 + r) * 96 + c];
        }
        __syncthreads();

        #pragma unroll
        for (int kk = 0; kk < BK; kk++) {
            float a[8], b[6];
            #pragma unroll
            for (int i = 0; i < 8; i++) a[i] = sA[kk][ty * 8 + i];
            #pragma unroll
            for (int j = 0; j < 6; j++) b[j] = sB[kk][tx * 6 + j];
            #pragma unroll
            for (int i = 0; i < 8; i++)
                #pragma unroll
                for (int j = 0; j < 6; j++) acc[i][j] += a[i] * b[j];
        }
        __syncthreads();
    }

    // K tail (K=500 -> 4 remaining columns), fully guarded, zero-padded
    if (KF < K) {
        #pragma unroll
        for (int hh = 0; hh < 2; hh++) {
            int r = lr + hh * 64;
            int gr = bm0 + r;
            float s = rsc[hh];
            #pragma unroll
            for (int q = 0; q < 4; q++) {
                int gc = KF + lc4 * 4 + q;
                float v = 0.f;
                if (gr < M && gc < K) v = A[gr * K + gc] * s;
                sA[lc4 * 4 + q][r] = v;
            }
        }
        #pragma unroll
        for (int hh = 0; hh < 6; hh++) {
            int idx = tid + hh * 256;
            int r = idx / 96, c = idx % 96;
            int gk = KF + r;
            sB[r][c] = (gk < K) ? B[gk * 96 + c] : 0.f;
        }
        __syncthreads();
        #pragma unroll
        for (int kk = 0; kk < BK; kk++) {
            float a[8], b[6];
            #pragma unroll
            for (int i = 0; i < 8; i++) a[i] = sA[kk][ty * 8 + i];
            #pragma unroll
            for (int j = 0; j < 6; j++) b[j] = sB[kk][tx * 6 + j];
            #pragma unroll
            for (int i = 0; i < 8; i++)
                #pragma unroll
                for (int j = 0; j < 6; j++) acc[i][j] += a[i] * b[j];
        }
        __syncthreads();
    }

    #pragma unroll
    for (int i = 0; i < 8; i++) {
        int gr = bm0 + ty * 8 + i;
        if (gr < M) {
            #pragma unroll
            for (int j = 0; j < 6; j++)
                C[gr * 96 + tx * 6 + j] = acc[i][j];
        }
    }
}

// ---------------- fused CSR SpMM + norm_in + bias + PReLU ----------------
// one block (96 threads) per dst node; each thread owns one channel.
// colw == nullptr -> unweighted gather (weights already folded into `in`).
__global__ void k_spmm(const float* __restrict__ in,
                       const int* __restrict__ colidx,
                       const float* __restrict__ colw,
                       float* __restrict__ out,
                       const float* __restrict__ b, const float* __restrict__ a) {
    int node = blockIdx.x;
    int j = threadIdx.x;
    int s = d_row_ptr[node], e = d_row_ptr[node + 1];
    float acc = 0.f;
    int i = s;
    if (colw) {
        for (; i + 4 <= e; i += 4) {
            int c0 = colidx[i],     c1 = colidx[i + 1];
            int c2 = colidx[i + 2], c3 = colidx[i + 3];
            float w0 = colw[i],     w1 = colw[i + 1];
            float w2 = colw[i + 2], w3 = colw[i + 3];
            acc += w0 * in[c0 * H + j] + w1 * in[c1 * H + j]
                 + w2 * in[c2 * H + j] + w3 * in[c3 * H + j];
        }
        for (; i < e; i++) acc += colw[i] * in[colidx[i] * H + j];
    } else {
        for (; i + 4 <= e; i += 4) {
            int c0 = colidx[i],     c1 = colidx[i + 1];
            int c2 = colidx[i + 2], c3 = colidx[i + 3];
            float v0 = in[c0 * H + j];
            float v1 = in[c1 * H + j];
            float v2 = in[c2 * H + j];
            float v3 = in[c3 * H + j];
            acc += (v0 + v1) + (v2 + v3);
        }
        for (; i < e; i++) acc += in[colidx[i] * H + j];
    }
    float v = acc * d_norm_in[node] + b[j];
    out[node * H + j] = (v >= 0.f) ? v : a[j] * v;
}

// ---------------- output: out[i] = h2[i,:] . wvec + bsum ----------------
__global__ void k_out(const float* __restrict__ h2, float* __restrict__ out) {
    int gw = (blockIdx.x * blockDim.x + threadIdx.x) >> 5;
    int lane = threadIdx.x & 31;
    if (gw >= N_NODES) return;
    const float* row = h2 + gw * H;
    float s = row[lane] * d_wvec[lane]
            + row[lane + 32] * d_wvec[lane + 32]
            + row[lane + 64] * d_wvec[lane + 64];
    #pragma unroll
    for (int off = 16; off > 0; off >>= 1)
        s += __shfl_xor_sync(0xffffffffu, s, off);
    if (lane == 0) out[gw] = s + d_bsum;
}

// ---------------- launch ----------------
extern "C" void kernel_launch(void* const* d_in, const int* in_sizes, int n_in,
                              void* d_out, int out_size) {
    const float* x    = (const float*)d_in[0];
    const int*   src  = (const int*)d_in[1];
    const int*   dst  = (const int*)d_in[2];
    const int*   perm = (const int*)d_in[3];
    const float* W1   = (const float*)d_in[4];
    const float* b1   = (const float*)d_in[5];
    const float* a1   = (const float*)d_in[6];
    const float* W2   = (const float*)d_in[7];
    const float* b2   = (const float*)d_in[8];
    const float* a2   = (const float*)d_in[9];
    const float* Wm   = (const float*)d_in[10];
    const float* bm   = (const float*)d_in[11];
    float* out = (float*)d_out;

    float *hY, *hH, *hT, *hNormOut, *hColw;
    int *hCol, *hCol2;
    cudaGetSymbolAddress((void**)&hY, d_Y);
    cudaGetSymbolAddress((void**)&hH, d_h);
    cudaGetSymbolAddress((void**)&hT, d_t);
    cudaGetSymbolAddress((void**)&hNormOut, d_norm_out);
    cudaGetSymbolAddress((void**)&hCol, d_col);
    cudaGetSymbolAddress((void**)&hCol2, d_col2);
    cudaGetSymbolAddress((void**)&hColw, d_colw);

    const int TB = 256;
    // graph structure
    k_zero_deg<<<(N_NODES + TB - 1) / TB, TB>>>();
    k_count<<<(N_EDGES + TB - 1) / TB, TB>>>(src, dst);
    k_norm<<<(N_NODES + TB - 1) / TB, TB>>>();
    k_scan1<<<NCHUNK, 1024>>>();
    k_scan2<<<1, 64>>>();
    k_scan3<<<(N_NODES + TB - 1) / TB, TB>>>();
    k_build_csr<<<(N_EDGES + TB - 1) / TB, TB>>>(src, dst, perm);
    k_fold<<<1, 128>>>(Wm, bm);

    // shared first-layer GEMM: Y = x @ W1 (norm_out folded into edge weights)
    int gm = (N_NODES + 127) / 128;
    sgemm_n96<<<gm, 256>>>(x, F_IN, W1, nullptr, hY, N_NODES);

    for (int v = 0; v < 2; v++) {
        const int* cidx = v ? hCol2 : hCol;
        // layer 1: weighted gather from Y + norm_in + bias + PReLU -> t
        k_spmm<<<N_NODES, H>>>(hY, cidx, hColw, hT, b1, a1);
        // layer 2 GEMM with fused norm_out row-scale: h = (t*norm_out) @ W2
        sgemm_n96<<<gm, 256>>>(hT, H, W2, hNormOut, hH, N_NODES);
        // layer 2: unweighted gather (norm_out folded into h) -> t
        k_spmm<<<N_NODES, H>>>(hH, hCol, nullptr, hT, b2, a2);
        // projected row-sum
        k_out<<<(N_NODES * 32 + TB - 1) / TB, TB>>>(hT, out + v * N_NODES);
    }
}

// round 7
// speedup vs baseline: 1.4407x; 1.4407x over previous
#include <cuda_runtime.h>

#define N_NODES 50000
#define N_EDGES 800000
#define F_IN    500
#define H       96
#define NCHUNK  ((N_NODES + 1023) / 1024)   // 49

// ---------------- device scratch (no allocations allowed) ----------------
__device__ float d_norm_out[N_NODES];
__device__ float d_norm_in[N_NODES];
__device__ int   d_deg_out[N_NODES];
__device__ int   d_deg_in[N_NODES];
__device__ int   d_row_ptr[N_NODES + 1];
__device__ int   d_cursor[N_NODES];
__device__ int   d_chunksum[NCHUNK];
__device__ int   d_chunkoff[NCHUNK];
__device__ int   d_col[N_EDGES];            // src ids grouped by dst
__device__ int   d_col2[N_EDGES];           // perm[src] grouped by dst (view 2)
__device__ float d_colw[N_EDGES];           // norm_out[src] per edge
__device__ float d_Y[N_NODES * H];          // x @ W1 (shared by both views)
__device__ float d_h[N_NODES * H];
__device__ float d_t[N_NODES * H];
__device__ float d_wvec[H];                 // Wm @ ones
__device__ float d_bsum;                    // sum(bm)

// ---------------- degree / norm ----------------
__global__ void k_zero_deg() {
    int i = blockIdx.x * blockDim.x + threadIdx.x;
    if (i < N_NODES) { d_deg_out[i] = 0; d_deg_in[i] = 0; }
}

__global__ void k_count(const int* __restrict__ src, const int* __restrict__ dst) {
    int e = blockIdx.x * blockDim.x + threadIdx.x;
    if (e < N_EDGES) {
        atomicAdd(&d_deg_out[src[e]], 1);
        atomicAdd(&d_deg_in[dst[e]], 1);
    }
}

__global__ void k_norm() {
    int i = blockIdx.x * blockDim.x + threadIdx.x;
    if (i < N_NODES) {
        int dor = d_deg_out[i]; if (dor < 1) dor = 1;
        int din = d_deg_in[i];  if (din < 1) din = 1;
        d_norm_out[i] = rsqrtf((float)dor);
        d_norm_in[i]  = rsqrtf((float)din);
    }
}

// ---------------- parallel exclusive scan (3 phases, proven 5.4us) ----------------
__global__ void k_scan1() {
    int tid = threadIdx.x;
    int i = blockIdx.x * 1024 + tid;
    int v = (i < N_NODES) ? d_deg_in[i] : 0;
    int lane = tid & 31, wid = tid >> 5;

    int inc = v;
    #pragma unroll
    for (int off = 1; off < 32; off <<= 1) {
        int t = __shfl_up_sync(0xffffffffu, inc, off);
        if (lane >= off) inc += t;
    }
    __shared__ int wsum[32];
    if (lane == 31) wsum[wid] = inc;
    __syncthreads();
    if (wid == 0) {
        int w = wsum[lane];
        #pragma unroll
        for (int off = 1; off < 32; off <<= 1) {
            int t = __shfl_up_sync(0xffffffffu, w, off);
            if (lane >= off) w += t;
        }
        wsum[lane] = w;
    }
    __syncthreads();
    int base = wid ? wsum[wid - 1] : 0;
    if (i < N_NODES) d_row_ptr[i] = base + inc - v;   // chunk-local exclusive
    if (tid == 1023) d_chunksum[blockIdx.x] = base + inc;
}

__global__ void k_scan2() {
    __shared__ int s[64];
    int tid = threadIdx.x;                  // 64 threads
    int v = (tid < NCHUNK) ? d_chunksum[tid] : 0;
    s[tid] = v;
    __syncthreads();
    #pragma unroll
    for (int off = 1; off < 64; off <<= 1) {
        int t = (tid >= off) ? s[tid - off] : 0;
        __syncthreads();
        s[tid] += t;
        __syncthreads();
    }
    if (tid < NCHUNK) d_chunkoff[tid] = s[tid] - v;   // exclusive
}

__global__ void k_scan3() {
    int i = blockIdx.x * blockDim.x + threadIdx.x;
    if (i < N_NODES) {
        int r = d_row_ptr[i] + d_chunkoff[i >> 10];
        d_row_ptr[i] = r;
        d_cursor[i] = r;
    }
    if (i == 0) d_row_ptr[N_NODES] = N_EDGES;
}

// ---------------- CSR build with folded edge data ----------------
__global__ void k_build_csr(const int* __restrict__ src, const int* __restrict__ dst,
                            const int* __restrict__ perm) {
    int e = blockIdx.x * blockDim.x + threadIdx.x;
    if (e < N_EDGES) {
        int d = dst[e];
        int s = src[e];
        int pos = atomicAdd(&d_cursor[d], 1);
        d_col[pos]  = s;
        d_col2[pos] = perm[s];
        d_colw[pos] = d_norm_out[s];
    }
}

// ---------------- fold Wm into a vector ----------------
__global__ void k_fold(const float* __restrict__ Wm, const float* __restrict__ bm) {
    int j = threadIdx.x;
    if (j < H) {
        float s = 0.f;
        #pragma unroll 4
        for (int k = 0; k < H; k++) s += Wm[j * H + k];
        d_wvec[j] = s;
    }
    if (j == H) {
        float s = 0.f;
        for (int k = 0; k < H; k++) s += bm[k];
        d_bsum = s;
    }
}

// ---------------- SGEMM: C[M,96] = (rowscale .* A[M,K]) @ B[K,96] ----------------
// REVERTED to R1 shape: BM=64, BN=96, BK=16, 256 threads, 4x6 micro-tile
// (~50 regs -> 4+ blocks/SM; 782-block grid; proven in the 577us config).
__global__ void sgemm_n96(const float* __restrict__ A, int K,
                          const float* __restrict__ B,
                          const float* __restrict__ rowscale,
                          float* __restrict__ C, int M) {
    const int BM = 64, BN = 96, BK = 16;
    __shared__ float sA[BK][BM + 1];
    __shared__ float sB[BK][BN];

    int tid = threadIdx.x;
    int tx = tid % 16;          // 16 col groups (6 cols each)
    int ty = tid / 16;          // 16 row groups (4 rows each)
    int bm0 = blockIdx.x * BM;

    float acc[4][6];
    #pragma unroll
    for (int i = 0; i < 4; i++)
        #pragma unroll
        for (int j = 0; j < 6; j++) acc[i][j] = 0.f;

    for (int k0 = 0; k0 < K; k0 += BK) {
        // load A tile (transposed into smem), apply optional row scale
        #pragma unroll
        for (int i = 0; i < (BM * BK) / 256; i++) {
            int idx = tid + i * 256;
            int r = idx / BK, c = idx % BK;
            int gr = bm0 + r, gc = k0 + c;
            float v = 0.f;
            if (gr < M && gc < K) {
                v = A[gr * K + gc];
                if (rowscale) v *= rowscale[gr];
            }
            sA[c][r] = v;
        }
        // load B tile
        #pragma unroll
        for (int i = 0; i < (BK * BN) / 256; i++) {
            int idx = tid + i * 256;
            int r = idx / BN, c = idx % BN;
            int gk = k0 + r;
            sB[r][c] = (gk < K) ? B[gk * BN + c] : 0.f;
        }
        __syncthreads();

        #pragma unroll
        for (int kk = 0; kk < BK; kk++) {
            float a[4], b[6];
            #pragma unroll
            for (int i = 0; i < 4; i++) a[i] = sA[kk][ty * 4 + i];
            #pragma unroll
            for (int j = 0; j < 6; j++) b[j] = sB[kk][tx * 6 + j];
            #pragma unroll
            for (int i = 0; i < 4; i++)
                #pragma unroll
                for (int j = 0; j < 6; j++) acc[i][j] += a[i] * b[j];
        }
        __syncthreads();
    }

    #pragma unroll
    for (int i = 0; i < 4; i++) {
        int gr = bm0 + ty * 4 + i;
        if (gr < M) {
            #pragma unroll
            for (int j = 0; j < 6; j++)
                C[gr * 96 + tx * 6 + j] = acc[i][j];
        }
    }
}

// ---------------- fused CSR SpMM + norm_in + bias + PReLU ----------------
// one block (96 threads) per dst node; each thread owns one channel.
// colw == nullptr -> unweighted gather (weights already folded into `in`).
__global__ void k_spmm(const float* __restrict__ in,
                       const int* __restrict__ colidx,
                       const float* __restrict__ colw,
                       float* __restrict__ out,
                       const float* __restrict__ b, const float* __restrict__ a) {
    int node = blockIdx.x;
    int j = threadIdx.x;
    int s = d_row_ptr[node], e = d_row_ptr[node + 1];
    float acc = 0.f;
    int i = s;
    if (colw) {
        for (; i + 4 <= e; i += 4) {
            int c0 = colidx[i],     c1 = colidx[i + 1];
            int c2 = colidx[i + 2], c3 = colidx[i + 3];
            float w0 = colw[i],     w1 = colw[i + 1];
            float w2 = colw[i + 2], w3 = colw[i + 3];
            acc += w0 * in[c0 * H + j] + w1 * in[c1 * H + j]
                 + w2 * in[c2 * H + j] + w3 * in[c3 * H + j];
        }
        for (; i < e; i++) acc += colw[i] * in[colidx[i] * H + j];
    } else {
        for (; i + 4 <= e; i += 4) {
            int c0 = colidx[i],     c1 = colidx[i + 1];
            int c2 = colidx[i + 2], c3 = colidx[i + 3];
            float v0 = in[c0 * H + j];
            float v1 = in[c1 * H + j];
            float v2 = in[c2 * H + j];
            float v3 = in[c3 * H + j];
            acc += (v0 + v1) + (v2 + v3);
        }
        for (; i < e; i++) acc += in[colidx[i] * H + j];
    }
    float v = acc * d_norm_in[node] + b[j];
    out[node * H + j] = (v >= 0.f) ? v : a[j] * v;
}

// ---------------- output: out[i] = h2[i,:] . wvec + bsum ----------------
__global__ void k_out(const float* __restrict__ h2, float* __restrict__ out) {
    int gw = (blockIdx.x * blockDim.x + threadIdx.x) >> 5;
    int lane = threadIdx.x & 31;
    if (gw >= N_NODES) return;
    const float* row = h2 + gw * H;
    float s = row[lane] * d_wvec[lane]
            + row[lane + 32] * d_wvec[lane + 32]
            + row[lane + 64] * d_wvec[lane + 64];
    #pragma unroll
    for (int off = 16; off > 0; off >>= 1)
        s += __shfl_xor_sync(0xffffffffu, s, off);
    if (lane == 0) out[gw] = s + d_bsum;
}

// ---------------- launch ----------------
extern "C" void kernel_launch(void* const* d_in, const int* in_sizes, int n_in,
                              void* d_out, int out_size) {
    const float* x    = (const float*)d_in[0];
    const int*   src  = (const int*)d_in[1];
    const int*   dst  = (const int*)d_in[2];
    const int*   perm = (const int*)d_in[3];
    const float* W1   = (const float*)d_in[4];
    const float* b1   = (const float*)d_in[5];
    const float* a1   = (const float*)d_in[6];
    const float* W2   = (const float*)d_in[7];
    const float* b2   = (const float*)d_in[8];
    const float* a2   = (const float*)d_in[9];
    const float* Wm   = (const float*)d_in[10];
    const float* bm   = (const float*)d_in[11];
    float* out = (float*)d_out;

    float *hY, *hH, *hT, *hNormOut, *hColw;
    int *hCol, *hCol2;
    cudaGetSymbolAddress((void**)&hY, d_Y);
    cudaGetSymbolAddress((void**)&hH, d_h);
    cudaGetSymbolAddress((void**)&hT, d_t);
    cudaGetSymbolAddress((void**)&hNormOut, d_norm_out);
    cudaGetSymbolAddress((void**)&hCol, d_col);
    cudaGetSymbolAddress((void**)&hCol2, d_col2);
    cudaGetSymbolAddress((void**)&hColw, d_colw);

    const int TB = 256;
    // graph structure
    k_zero_deg<<<(N_NODES + TB - 1) / TB, TB>>>();
    k_count<<<(N_EDGES + TB - 1) / TB, TB>>>(src, dst);
    k_norm<<<(N_NODES + TB - 1) / TB, TB>>>();
    k_scan1<<<NCHUNK, 1024>>>();
    k_scan2<<<1, 64>>>();
    k_scan3<<<(N_NODES + TB - 1) / TB, TB>>>();
    k_build_csr<<<(N_EDGES + TB - 1) / TB, TB>>>(src, dst, perm);
    k_fold<<<1, 128>>>(Wm, bm);

    // shared first-layer GEMM: Y = x @ W1 (norm_out folded into edge weights)
    int gm = (N_NODES + 63) / 64;
    sgemm_n96<<<gm, 256>>>(x, F_IN, W1, nullptr, hY, N_NODES);

    for (int v = 0; v < 2; v++) {
        const int* cidx = v ? hCol2 : hCol;
        // layer 1: weighted gather from Y + norm_in + bias + PReLU -> t
        k_spmm<<<N_NODES, H>>>(hY, cidx, hColw, hT, b1, a1);
        // layer 2 GEMM with fused norm_out row-scale: h = (t*norm_out) @ W2
        sgemm_n96<<<gm, 256>>>(hT, H, W2, hNormOut, hH, N_NODES);
        // layer 2: unweighted gather (norm_out folded into h) -> t
        k_spmm<<<N_NODES, H>>>(hH, hCol, nullptr, hT, b2, a2);
        // projected row-sum
        k_out<<<(N_NODES * 32 + TB - 1) / TB, TB>>>(hT, out + v * N_NODES);
    }
}